// round 1
// baseline (speedup 1.0000x reference)
#include <cuda_runtime.h>
#include <math.h>

// Static device scratch: winner edge-id (+1) per (u,v) cell. 4096*4096 ints = 64 MiB.
// Static __device__ global => no runtime allocation (allowed by harness rules).
#define N_MAX 4096
__device__ int g_winner[(size_t)N_MAX * N_MAX];

// ---------------------------------------------------------------------------
// Kernel 1: claim — deterministic last-write-wins via atomicMax on edge id+1.
// Reference (JAX CPU scatter) applies updates sequentially in edge order, so
// the highest edge index wins at duplicate (u,v) positions.
// ---------------------------------------------------------------------------
__global__ void edgebias_claim_kernel(const int* __restrict__ edge_index,
                                      int E, int N) {
    int e = blockIdx.x * blockDim.x + threadIdx.x;
    if (e >= E) return;
    int u = edge_index[e];
    int v = edge_index[E + e];
    atomicMax(&g_winner[(size_t)u * N + v], e + 1);
}

// ---------------------------------------------------------------------------
// Kernel 2: write — winners compute scores = attr_row @ W + b (D=128, H=8)
// and scatter into the 8 head planes. W (4 KB) and b staged in shared memory.
// ---------------------------------------------------------------------------
__global__ void edgebias_write_kernel(const int* __restrict__ edge_index,
                                      const float* __restrict__ edge_attr,
                                      const float* __restrict__ W,
                                      const float* __restrict__ b,
                                      float* __restrict__ out,
                                      int E, int N) {
    __shared__ float sW[128 * 8];
    __shared__ float sb[8];
    for (int i = threadIdx.x; i < 128 * 8; i += blockDim.x) sW[i] = W[i];
    if (threadIdx.x < 8) sb[threadIdx.x] = b[threadIdx.x];
    __syncthreads();

    int e = blockIdx.x * blockDim.x + threadIdx.x;
    if (e >= E) return;

    int u = edge_index[e];
    int v = edge_index[E + e];
    size_t cell = (size_t)u * N + v;

    // Only the last edge targeting this (u,v) writes.
    if (g_winner[cell] != e + 1) return;

    float acc[8];
#pragma unroll
    for (int h = 0; h < 8; h++) acc[h] = sb[h];

    const float4* row = reinterpret_cast<const float4*>(edge_attr + (size_t)e * 128);
#pragma unroll
    for (int i = 0; i < 32; i++) {
        float4 a = row[i];
        const float* w0 = &sW[(4 * i + 0) * 8];
        const float* w1 = &sW[(4 * i + 1) * 8];
        const float* w2 = &sW[(4 * i + 2) * 8];
        const float* w3 = &sW[(4 * i + 3) * 8];
#pragma unroll
        for (int h = 0; h < 8; h++) {
            acc[h] += a.x * w0[h];
            acc[h] += a.y * w1[h];
            acc[h] += a.z * w2[h];
            acc[h] += a.w * w3[h];
        }
    }

    size_t NN = (size_t)N * N;
#pragma unroll
    for (int h = 0; h < 8; h++) {
        out[(size_t)h * NN + cell] = acc[h];
    }
}

// ---------------------------------------------------------------------------
// Launch. Inputs (metadata order): edge_index[2,E] i32, edge_attr[E,128] f32,
// W[128,8] f32, b[8] f32, num_nodes (scalar, ignored; N derived from out_size).
// ---------------------------------------------------------------------------
extern "C" void kernel_launch(void* const* d_in, const int* in_sizes, int n_in,
                              void* d_out, int out_size) {
    const int*   edge_index = (const int*)d_in[0];
    const float* edge_attr  = (const float*)d_in[1];
    const float* W          = (const float*)d_in[2];
    const float* b          = (const float*)d_in[3];
    float*       out        = (float*)d_out;

    int E = in_sizes[0] / 2;          // 131072
    int H = in_sizes[3];              // 8
    // out_size = H * N * N  ->  N
    double nn = (double)out_size / (double)H;
    int N = (int)(sqrt(nn) + 0.5);    // 4096

    // 1) zero output (512 MiB) + winner scratch (N*N ints) via memset nodes.
    void* winner_ptr = nullptr;
    cudaGetSymbolAddress(&winner_ptr, g_winner);
    cudaMemsetAsync(winner_ptr, 0, (size_t)N * N * sizeof(int), 0);
    cudaMemsetAsync(out, 0, (size_t)out_size * sizeof(float), 0);

    // 2) claim winners (last edge id wins).
    int threads = 256;
    int blocks = (E + threads - 1) / threads;
    edgebias_claim_kernel<<<blocks, threads>>>(edge_index, E, N);

    // 3) winners compute 8-head scores and scatter.
    edgebias_write_kernel<<<blocks, threads>>>(edge_index, edge_attr, W, b,
                                               out, E, N);
}